// round 7
// baseline (speedup 1.0000x reference)
#include <cuda_runtime.h>

#define NF 39
#define NV 200000
#define NB 16384
#define RPB 64             // rows per block
#define NT  256            // 8 warps
#define GRID (NB / RPB)    // 256

// ---------- f32x2 packed helpers (sm_103a FFMA2, PTX-only) ----------
static __device__ __forceinline__ unsigned long long pack2(float a, float b) {
    unsigned long long r;
    asm("mov.b64 %0, {%1, %2};" : "=l"(r) : "f"(a), "f"(b));
    return r;
}
static __device__ __forceinline__ unsigned long long splat2(float a) {
    unsigned long long r;
    asm("mov.b64 %0, {%1, %1};" : "=l"(r) : "f"(a));
    return r;
}
static __device__ __forceinline__ void ffma2(unsigned long long& acc,
                                             unsigned long long a,
                                             unsigned long long b) {
    asm("fma.rn.f32x2 %0, %1, %2, %0;" : "+l"(acc) : "l"(a), "l"(b));
}
static __device__ __forceinline__ void unpack2(unsigned long long v, float& lo, float& hi) {
    asm("mov.b64 {%0, %1}, %2;" : "=f"(lo), "=f"(hi) : "l"(v));
}

// ---------- smem layout (bytes) ----------
// ebuf : 2 x 64 rows x 20 floats (pad stride 20 -> conflict-free)   = 10240
// wbuf : 2 x 16 e x 34 ull (pad 34 for STS conflicts)               =  8704
// mlp  : 2176 floats                                                =  8704
// Xis  : 64*39 int                                                  =  9984
// Xvs  : 64*39 float                                                =  9984
#define OFF_EB   0
#define OFF_WB   10240
#define OFF_MLP  18944
#define OFF_XIS  27648
#define OFF_XVS  37632
#define SMEM_TOT 47616
// aliases after mainloop:
#define OFF_XB   OFF_EB     // 64*33 floats = 8448 <= 10240
#define OFF_YB   OFF_XIS    // 8448 <= 9984

#define WSTRIDE 34          // ull per e-row in wbuf

extern __shared__ unsigned char smem_raw[];

__global__ void __launch_bounds__(NT, 3)
pnn_fused(const int* __restrict__ Xi, const float* __restrict__ Xv,
          const float* __restrict__ tables,
          const float* __restrict__ W1, const float* __restrict__ Wi,
          const float* __restrict__ l1w, const float* __restrict__ l1b,
          const float* __restrict__ l2w, const float* __restrict__ l2b,
          const float* __restrict__ lw, const float* __restrict__ lb,
          float* __restrict__ out)
{
    float* ebuf = reinterpret_cast<float*>(smem_raw + OFF_EB);                 // [2][64*20]
    unsigned long long* wbuf = reinterpret_cast<unsigned long long*>(smem_raw + OFF_WB); // [2][16*34]
    float* mlp  = reinterpret_cast<float*>(smem_raw + OFF_MLP);
    int*   Xis  = reinterpret_cast<int*>(smem_raw + OFF_XIS);
    float* Xvs  = reinterpret_cast<float*>(smem_raw + OFF_XVS);

    const int tid = threadIdx.x;
    const int wid = tid >> 5, lid = tid & 31;

    // ---- stage Xi/Xv slice + MLP weights ----
    {
        const long gbase = (long)blockIdx.x * RPB * NF;
        for (int i = tid; i < RPB * NF; i += NT) { Xis[i] = Xi[gbase + i]; Xvs[i] = Xv[gbase + i]; }
        for (int i = tid; i < 1024; i += NT) { mlp[i] = l1w[i]; mlp[1024 + i] = l2w[i]; }
        if (tid < 32) {
            mlp[2048 + tid] = l1b[tid];
            mlp[2080 + tid] = l2b[tid];
            mlp[2112 + tid] = lw[tid];
            if (tid == 0) mlp[2144] = lb[0];
        }
    }
    __syncthreads();   // Xis ready for gather

    const int gr = tid >> 2, gq = tid & 3;          // emb gather: 4 threads/row, 16B each
    const int wd = tid >> 2, weq = tid & 3;         // weight load (tid<128): d=wd, e-quad
    const float4* tab4 = reinterpret_cast<const float4*>(tables);

    // ---- stage field 0 into buffer 0 ----
    {
        int   idx = Xis[gr * NF];
        float v   = Xvs[gr * NF];
        float4 t = tab4[((long)0 * NV + idx) * 4 + gq];
        *reinterpret_cast<float4*>(ebuf + gr * 20 + gq * 4) =
            make_float4(t.x * v, t.y * v, t.z * v, t.w * v);
        if (tid < 128) {
            int g = wd * (NF * 16) + 0 * 16 + weq * 4;
            float4 a = *reinterpret_cast<const float4*>(W1 + g);
            float4 b = *reinterpret_cast<const float4*>(Wi + g);
            unsigned long long* wb = wbuf;
            wb[(weq * 4 + 0) * WSTRIDE + wd] = pack2(a.x, b.x);
            wb[(weq * 4 + 1) * WSTRIDE + wd] = pack2(a.y, b.y);
            wb[(weq * 4 + 2) * WSTRIDE + wd] = pack2(a.z, b.z);
            wb[(weq * 4 + 3) * WSTRIDE + wd] = pack2(a.w, b.w);
        }
    }
    __syncthreads();

    // ---- compute assignment: warp dq owns d in [dq*4, dq*4+4); lane owns rows lid, lid+32 ----
    const int dq = wid;
    const int rA = lid, rB = lid + 32;

    unsigned long long accA[4] = {0ull, 0ull, 0ull, 0ull};
    unsigned long long accB[4] = {0ull, 0ull, 0ull, 0ull};

    for (int f = 0; f < NF; f++) {
        const int p = f & 1;
        const bool pf = (f + 1 < NF);

        // ---- prefetch field f+1 (LDG issued before compute) ----
        float4 et; float ev = 0.0f;
        float4 pa, pb;
        if (pf) {
            int   idx = Xis[gr * NF + f + 1];
            ev = Xvs[gr * NF + f + 1];
            et = tab4[((long)(f + 1) * NV + idx) * 4 + gq];
            if (tid < 128) {
                int g = wd * (NF * 16) + (f + 1) * 16 + weq * 4;
                pa = *reinterpret_cast<const float4*>(W1 + g);
                pb = *reinterpret_cast<const float4*>(Wi + g);
            }
        }

        // ---- compute field f from buffers[p] ----
        {
            const float* ep = ebuf + p * (RPB * 20);
            const unsigned long long* wp = wbuf + p * (16 * WSTRIDE);

            float ar[16], br[16];
            {
                const float4* a4 = reinterpret_cast<const float4*>(ep + rA * 20);
                const float4* b4 = reinterpret_cast<const float4*>(ep + rB * 20);
#pragma unroll
                for (int j = 0; j < 4; j++) {
                    float4 qa = a4[j], qb = b4[j];
                    ar[4 * j] = qa.x; ar[4 * j + 1] = qa.y; ar[4 * j + 2] = qa.z; ar[4 * j + 3] = qa.w;
                    br[4 * j] = qb.x; br[4 * j + 1] = qb.y; br[4 * j + 2] = qb.z; br[4 * j + 3] = qb.w;
                }
            }
#pragma unroll
            for (int e = 0; e < 16; e++) {
                const ulonglong2* w2 =
                    reinterpret_cast<const ulonglong2*>(wp + e * WSTRIDE) + dq * 2;
                ulonglong2 w01 = w2[0];          // d = 4dq, 4dq+1  (broadcast LDS.128)
                ulonglong2 w23 = w2[1];          // d = 4dq+2, 4dq+3
                unsigned long long sA = splat2(ar[e]);
                unsigned long long sB = splat2(br[e]);
                ffma2(accA[0], sA, w01.x); ffma2(accA[1], sA, w01.y);
                ffma2(accA[2], sA, w23.x); ffma2(accA[3], sA, w23.y);
                ffma2(accB[0], sB, w01.x); ffma2(accB[1], sB, w01.y);
                ffma2(accB[2], sB, w23.x); ffma2(accB[3], sB, w23.y);
            }
        }

        // ---- store prefetched field into buffers[p^1] ----
        if (pf) {
            float* ed = ebuf + (p ^ 1) * (RPB * 20);
            *reinterpret_cast<float4*>(ed + gr * 20 + gq * 4) =
                make_float4(et.x * ev, et.y * ev, et.z * ev, et.w * ev);
            if (tid < 128) {
                unsigned long long* wb = wbuf + (p ^ 1) * (16 * WSTRIDE);
                wb[(weq * 4 + 0) * WSTRIDE + wd] = pack2(pa.x, pb.x);
                wb[(weq * 4 + 1) * WSTRIDE + wd] = pack2(pa.y, pb.y);
                wb[(weq * 4 + 2) * WSTRIDE + wd] = pack2(pa.z, pb.z);
                wb[(weq * 4 + 3) * WSTRIDE + wd] = pack2(pa.w, pb.w);
            }
        }
        __syncthreads();
    }

    // ---- x = first_order + s^2 into xb ----
    float* xb = reinterpret_cast<float*>(smem_raw + OFF_XB);
    float* yb = reinterpret_cast<float*>(smem_raw + OFF_YB);
#pragma unroll
    for (int j = 0; j < 4; j++) {
        int d = dq * 4 + j;
        float fo, sv;
        unpack2(accA[j], fo, sv);
        xb[rA * 33 + d] = fmaf(sv, sv, fo);
        unpack2(accB[j], fo, sv);
        xb[rB * 33 + d] = fmaf(sv, sv, fo);
    }
    __syncthreads();

    // ---- MLP: 4 threads per row, 8 outputs each ----
    const int q = tid & 3, rr = tid >> 2;
    {
        const float* xr = xb + rr * 33;
#pragma unroll
        for (int j = 0; j < 8; j++) {
            int jj = q * 8 + j;
            float s = mlp[2048 + jj];
            const float* wrow = mlp + jj * 32;
#pragma unroll
            for (int k = 0; k < 32; k++) s = fmaf(xr[k], wrow[k], s);
            yb[rr * 33 + jj] = fmaxf(s, 0.0f);
        }
    }
    __syncthreads();
    {
        const float* yr = yb + rr * 33;
#pragma unroll
        for (int j = 0; j < 8; j++) {
            int jj = q * 8 + j;
            float s = mlp[2080 + jj];
            const float* wrow = mlp + 1024 + jj * 32;
#pragma unroll
            for (int k = 0; k < 32; k++) s = fmaf(yr[k], wrow[k], s);
            xb[rr * 33 + jj] = fmaxf(s, 0.0f);
        }
    }
    __syncthreads();
    if (q == 0) {
        float s = mlp[2144];
        const float* zr = xb + rr * 33;
#pragma unroll
        for (int k = 0; k < 32; k++) s = fmaf(zr[k], mlp[2112 + k], s);
        out[blockIdx.x * RPB + rr] = s;
    }
}

extern "C" void kernel_launch(void* const* d_in, const int* in_sizes, int n_in,
                              void* d_out, int out_size)
{
    const int*   Xi     = (const int*)  d_in[0];
    const float* Xv     = (const float*)d_in[1];
    const float* tables = (const float*)d_in[2];
    const float* W1     = (const float*)d_in[3];
    const float* Wi     = (const float*)d_in[4];
    const float* l1w    = (const float*)d_in[5];
    const float* l1b    = (const float*)d_in[6];
    const float* l2w    = (const float*)d_in[7];
    const float* l2b    = (const float*)d_in[8];
    const float* lw     = (const float*)d_in[9];
    const float* lb     = (const float*)d_in[10];

    cudaFuncSetAttribute(pnn_fused, cudaFuncAttributeMaxDynamicSharedMemorySize, SMEM_TOT);

    pnn_fused<<<GRID, NT, SMEM_TOT>>>(
        Xi, Xv, tables, W1, Wi, l1w, l1b, l2w, l2b, lw, lb, (float*)d_out);
}

// round 8
// speedup vs baseline: 1.1327x; 1.1327x over previous
#include <cuda_runtime.h>

#define NF 39
#define NV 200000
#define NB 16384
#define RPB 64
#define NT 256
#define GRID (NB / RPB)     // 256

// ---------- f32x2 helpers ----------
static __device__ __forceinline__ unsigned long long pack2(float a, float b) {
    unsigned long long r;
    asm("mov.b64 %0, {%1, %2};" : "=l"(r) : "f"(a), "f"(b));
    return r;
}
static __device__ __forceinline__ void ffma2(unsigned long long& acc,
                                             unsigned long long a,
                                             unsigned long long b) {
    asm("fma.rn.f32x2 %0, %1, %2, %0;" : "+l"(acc) : "l"(a), "l"(b));
}
static __device__ __forceinline__ void unpack2(unsigned long long v, float& lo, float& hi) {
    asm("mov.b64 {%0, %1}, %2;" : "=f"(lo), "=f"(hi) : "l"(v));
}

// transposed packed weights: [f][j=e-pair][d] -> { (W1[d,f,2j],W1[d,f,2j+1]), (Wi...) }
static __device__ ulonglong2 g_wt[NF * 8 * 32];   // 160KB

__global__ void __launch_bounds__(256)
prep_wt(const float* __restrict__ W1, const float* __restrict__ Wi)
{
    int i = blockIdx.x * blockDim.x + threadIdx.x;   // i = d*312 + f*8 + j  (read-coalesced)
    if (i >= 32 * 312) return;
    int d = i / 312;
    int rem = i - d * 312;
    int f = rem >> 3, j = rem & 7;
    const float* p1 = W1 + d * (NF * 16) + f * 16 + 2 * j;
    const float* pi = Wi + d * (NF * 16) + f * 16 + 2 * j;
    ulonglong2 v;
    v.x = pack2(p1[0], p1[1]);
    v.y = pack2(pi[0], pi[1]);
    g_wt[(f * 8 + j) * 32 + d] = v;
}

// ---------- smem layout (bytes) ----------
#define OFF_EB   0          // 8 warps x 2 x 8 rows x 16 floats = 8192
#define OFF_XIS  8192       // 64*39 int   = 9984
#define OFF_XVS  18176      // 64*39 float = 9984
#define OFF_MLP  28160      // 2176 floats = 8704
#define OFF_XB   36864      // 64*33 floats = 8448
#define OFF_YB   45312      // 8448
#define SMEM_TOT 53760

extern __shared__ unsigned char smem_raw[];

__global__ void __launch_bounds__(NT, 2)
pnn_main(const int* __restrict__ Xi, const float* __restrict__ Xv,
         const float* __restrict__ tables,
         const float* __restrict__ l1w, const float* __restrict__ l1b,
         const float* __restrict__ l2w, const float* __restrict__ l2b,
         const float* __restrict__ lw, const float* __restrict__ lb,
         float* __restrict__ out)
{
    float* ebuf = reinterpret_cast<float*>(smem_raw + OFF_EB);
    int*   Xis  = reinterpret_cast<int*>(smem_raw + OFF_XIS);
    float* Xvs  = reinterpret_cast<float*>(smem_raw + OFF_XVS);
    float* mlp  = reinterpret_cast<float*>(smem_raw + OFF_MLP);
    float* xb   = reinterpret_cast<float*>(smem_raw + OFF_XB);
    float* yb   = reinterpret_cast<float*>(smem_raw + OFF_YB);

    const int tid = threadIdx.x;
    const int w = tid >> 5, lane = tid & 31;

    // ---- stage Xi/Xv slice + MLP weights ----
    {
        const long gbase = (long)blockIdx.x * RPB * NF;
        for (int i = tid; i < RPB * NF; i += NT) { Xis[i] = Xi[gbase + i]; Xvs[i] = Xv[gbase + i]; }
        for (int i = tid; i < 1024; i += NT) { mlp[i] = l1w[i]; mlp[1024 + i] = l2w[i]; }
        if (tid < 32) {
            mlp[2048 + tid] = l1b[tid];
            mlp[2080 + tid] = l2b[tid];
            mlp[2112 + tid] = lw[tid];
            if (tid == 0) mlp[2144] = lb[0];
        }
    }
    __syncthreads();

    // warp-private emb staging: warp w owns local rows [8w, 8w+8)
    float* eb = ebuf + w * (2 * 8 * 16);
    const int gr = lane >> 2, gq = lane & 3;        // gather: lane -> (row, 16B quad)
    const int lr = w * 8 + gr;                      // local row for gather
    const float4* tab4 = reinterpret_cast<const float4*>(tables);

    // ---- prologue: gather field 0 into phase 0 ----
    {
        int   idx = Xis[lr * NF];
        float v   = Xvs[lr * NF];
        float4 t  = __ldcg(tab4 + ((long)0 * NV + idx) * 4 + gq);
        *reinterpret_cast<float4*>(eb + gr * 16 + gq * 4) =
            make_float4(t.x * v, t.y * v, t.z * v, t.w * v);
    }
    __syncwarp();

    unsigned long long accfo[8], accs[8];
#pragma unroll
    for (int r = 0; r < 8; r++) { accfo[r] = 0ull; accs[r] = 0ull; }

    for (int f = 0; f < NF; f++) {
        const int p = f & 1;
        const bool pf = (f + 1 < NF);

        // ---- issue next field's gather early ----
        float4 tn; float vn = 0.0f;
        if (pf) {
            int idx = Xis[lr * NF + f + 1];
            vn = Xvs[lr * NF + f + 1];
            tn = __ldcg(tab4 + ((long)(f + 1) * NV + idx) * 4 + gq);
        }

        // ---- load this field's weights into registers (coalesced; L1-hot across warps) ----
        ulonglong2 wreg[8];
#pragma unroll
        for (int j = 0; j < 8; j++) wreg[j] = g_wt[(f * 8 + j) * 32 + lane];

        // ---- compute 8 rows: emb pairs broadcast from smem, e-parity packed ----
#pragma unroll
        for (int r = 0; r < 8; r++) {
            const ulonglong2* ep =
                reinterpret_cast<const ulonglong2*>(eb + p * 128 + r * 16);
            ulonglong2 eA = ep[0];   // (e0,e1),(e2,e3)
            ulonglong2 eB = ep[1];   // (e4,e5),(e6,e7)
            ulonglong2 eC = ep[2];
            ulonglong2 eD = ep[3];
            ffma2(accfo[r], eA.x, wreg[0].x); ffma2(accs[r], eA.x, wreg[0].y);
            ffma2(accfo[r], eA.y, wreg[1].x); ffma2(accs[r], eA.y, wreg[1].y);
            ffma2(accfo[r], eB.x, wreg[2].x); ffma2(accs[r], eB.x, wreg[2].y);
            ffma2(accfo[r], eB.y, wreg[3].x); ffma2(accs[r], eB.y, wreg[3].y);
            ffma2(accfo[r], eC.x, wreg[4].x); ffma2(accs[r], eC.x, wreg[4].y);
            ffma2(accfo[r], eC.y, wreg[5].x); ffma2(accs[r], eC.y, wreg[5].y);
            ffma2(accfo[r], eD.x, wreg[6].x); ffma2(accs[r], eD.x, wreg[6].y);
            ffma2(accfo[r], eD.y, wreg[7].x); ffma2(accs[r], eD.y, wreg[7].y);
        }

        // ---- stage prefetched field into other phase ----
        if (pf) {
            *reinterpret_cast<float4*>(eb + (p ^ 1) * 128 + gr * 16 + gq * 4) =
                make_float4(tn.x * vn, tn.y * vn, tn.z * vn, tn.w * vn);
        }
        __syncwarp();
    }

    // ---- horizontal add (e-parity) + s^2; lane owns d ----
#pragma unroll
    for (int r = 0; r < 8; r++) {
        float a, b;
        unpack2(accfo[r], a, b); float fo = a + b;
        unpack2(accs[r],  a, b); float sv = a + b;
        xb[(w * 8 + r) * 33 + lane] = fmaf(sv, sv, fo);
    }
    __syncthreads();

    // ---- MLP: 4 threads per row ----
    const int q = tid & 3, rr = tid >> 2;
    {
        const float* xr = xb + rr * 33;
#pragma unroll
        for (int j = 0; j < 8; j++) {
            int jj = q * 8 + j;
            float s = mlp[2048 + jj];
            const float* wrow = mlp + jj * 32;
#pragma unroll
            for (int k = 0; k < 32; k++) s = fmaf(xr[k], wrow[k], s);
            yb[rr * 33 + jj] = fmaxf(s, 0.0f);
        }
    }
    __syncthreads();
    {
        const float* yr = yb + rr * 33;
#pragma unroll
        for (int j = 0; j < 8; j++) {
            int jj = q * 8 + j;
            float s = mlp[2080 + jj];
            const float* wrow = mlp + 1024 + jj * 32;
#pragma unroll
            for (int k = 0; k < 32; k++) s = fmaf(yr[k], wrow[k], s);
            xb[rr * 33 + jj] = fmaxf(s, 0.0f);
        }
    }
    __syncthreads();
    if (q == 0) {
        float s = mlp[2144];
        const float* zr = xb + rr * 33;
#pragma unroll
        for (int k = 0; k < 32; k++) s = fmaf(zr[k], mlp[2112 + k], s);
        out[blockIdx.x * RPB + rr] = s;
    }
}

extern "C" void kernel_launch(void* const* d_in, const int* in_sizes, int n_in,
                              void* d_out, int out_size)
{
    const int*   Xi     = (const int*)  d_in[0];
    const float* Xv     = (const float*)d_in[1];
    const float* tables = (const float*)d_in[2];
    const float* W1     = (const float*)d_in[3];
    const float* Wi     = (const float*)d_in[4];
    const float* l1w    = (const float*)d_in[5];
    const float* l1b    = (const float*)d_in[6];
    const float* l2w    = (const float*)d_in[7];
    const float* l2b    = (const float*)d_in[8];
    const float* lw     = (const float*)d_in[9];
    const float* lb     = (const float*)d_in[10];

    prep_wt<<<(32 * 312 + 255) / 256, 256>>>(W1, Wi);

    cudaFuncSetAttribute(pnn_main, cudaFuncAttributeMaxDynamicSharedMemorySize, SMEM_TOT);
    pnn_main<<<GRID, NT, SMEM_TOT>>>(
        Xi, Xv, tables, l1w, l1b, l2w, l2b, lw, lb, (float*)d_out);
}